// round 1
// baseline (speedup 1.0000x reference)
#include <cuda_runtime.h>
#include <math.h>

#define NN   262144
#define EE   2097152
#define HID  200
#define TM   64
#define PADW 208
#define KT   50
#define SMEM_BYTES ((TM * PADW + KT * PADW) * 4)

// Scratch (static device globals: allowed; no dynamic allocation anywhere)
__device__ float g_deg[NN];
__device__ float g_inv[NN];
__device__ float g_agg[NN];
__device__ int   g_is64;

struct Params {
    const float* W[8];
    const float* b[8];
};

// ---------------------------------------------------------------------------
// Detect whether edge_index is int64 or int32.
// Values are in [0, 262144) so if int64 (little-endian), every odd 32-bit
// word of the first 64 elements is 0. For genuine int32 data the odds of 64
// random node ids all being zero are ~0.
// ---------------------------------------------------------------------------
__global__ void detect_kernel(const int* __restrict__ ei32) {
    if (blockIdx.x == 0 && threadIdx.x == 0) {
        int orv = 0;
        for (int i = 1; i < 128; i += 2) orv |= ei32[i];
        g_is64 = (orv == 0) ? 1 : 0;
    }
}

__device__ __forceinline__ int load_idx(const void* ei, long long pos, int is64) {
    if (is64) return (int)((const long long*)ei)[pos];
    return ((const int*)ei)[pos];
}

__global__ void zero_deg_kernel() {
    int i = blockIdx.x * blockDim.x + threadIdx.x;
    if (i < NN) g_deg[i] = 0.0f;
}

__global__ void deg_kernel(const void* __restrict__ ei) {
    const int is64 = g_is64;
    long long stride = (long long)gridDim.x * blockDim.x;
    for (long long e = (long long)blockIdx.x * blockDim.x + threadIdx.x; e < EE; e += stride) {
        int d = load_idx(ei, (long long)EE + e, is64);
        atomicAdd(&g_deg[d], 1.0f);
    }
}

// inv_sqrt of (indeg + 1) [self loop], and initialize agg with the self-loop term.
__global__ void inv_init_kernel(const float* __restrict__ x) {
    int i = blockIdx.x * blockDim.x + threadIdx.x;
    if (i < NN) {
        float inv = rsqrtf(g_deg[i] + 1.0f);  // deg >= 1 with self loop
        g_inv[i] = inv;
        g_agg[i] = x[i] * inv * inv;          // self-loop message
    }
}

__global__ void edge_agg_kernel(const float* __restrict__ x, const void* __restrict__ ei) {
    const int is64 = g_is64;
    long long stride = (long long)gridDim.x * blockDim.x;
    for (long long e = (long long)blockIdx.x * blockDim.x + threadIdx.x; e < EE; e += stride) {
        int s = load_idx(ei, e, is64);
        int d = load_idx(ei, (long long)EE + e, is64);
        atomicAdd(&g_agg[d], x[s] * g_inv[s] * g_inv[d]);
    }
}

// ---------------------------------------------------------------------------
// Fully fused 8-layer MLP. One CTA = 64 rows. Activations [64][208] in smem,
// weight K-tiles [50][208] streamed from L2. 16x16 thread grid, each thread
// owns a 4x13 register tile -> 52 FMA per 17 LDS per k step (FFMA-bound).
// ---------------------------------------------------------------------------
__global__ void __launch_bounds__(256, 2) mlp_kernel(Params p, float* __restrict__ out) {
    extern __shared__ float sm[];
    float* act = sm;                 // TM x PADW
    float* wt  = sm + TM * PADW;     // KT x PADW

    const int tid  = threadIdx.x;
    const int row0 = blockIdx.x * TM;
    const int tr   = tid >> 4;       // 0..15 (row group)
    const int tc   = tid & 15;       // 0..15 (col group)

    // ---- layer 0: [N,1] @ [1,200] + b, relu ----
    {
        const float* W0 = p.W[0];
        const float* b0 = p.b[0];
        for (int idx = tid; idx < TM * PADW; idx += 256) {
            int r = idx / PADW;
            int j = idx - r * PADW;
            float v = 0.0f;
            if (j < HID) v = fmaxf(fmaf(g_agg[row0 + r], W0[j], b0[j]), 0.0f);
            act[idx] = v;
        }
        __syncthreads();
    }

    // ---- layers 1..6: [64,200] @ [200,200] + b, relu ----
    for (int l = 1; l <= 6; ++l) {
        const float* __restrict__ W = p.W[l];
        const float* __restrict__ b = p.b[l];

        float acc[4][13];
        #pragma unroll
        for (int i = 0; i < 4; ++i)
            #pragma unroll
            for (int m = 0; m < 13; ++m) acc[i][m] = 0.0f;

        for (int k0 = 0; k0 < HID; k0 += KT) {
            // stage W k-tile into shared (zero-pad cols 200..207)
            for (int idx = tid; idx < KT * PADW; idx += 256) {
                int kk = idx / PADW;
                int j  = idx - kk * PADW;
                wt[idx] = (j < HID) ? W[(k0 + kk) * HID + j] : 0.0f;
            }
            __syncthreads();

            #pragma unroll 2
            for (int kk = 0; kk < KT; ++kk) {
                const int k = k0 + kk;
                float a[4];
                #pragma unroll
                for (int i = 0; i < 4; ++i) a[i] = act[(tr * 4 + i) * PADW + k];
                float w[13];
                #pragma unroll
                for (int m = 0; m < 13; ++m) w[m] = wt[kk * PADW + tc + 16 * m];
                #pragma unroll
                for (int i = 0; i < 4; ++i)
                    #pragma unroll
                    for (int m = 0; m < 13; ++m)
                        acc[i][m] = fmaf(a[i], w[m], acc[i][m]);
            }
            __syncthreads();
        }

        // writeback with bias + relu (all reads of act are done: safe in-place)
        #pragma unroll
        for (int i = 0; i < 4; ++i) {
            int r = tr * 4 + i;
            #pragma unroll
            for (int m = 0; m < 13; ++m) {
                int j = tc + 16 * m;
                float v = 0.0f;
                if (j < HID) v = fmaxf(acc[i][m] + b[j], 0.0f);
                act[r * PADW + j] = v;
            }
        }
        __syncthreads();
    }

    // ---- layer 7: [64,200] @ [200,1] + b, sigmoid ----
    if (tid < TM) {
        const float* __restrict__ W7 = p.W[7];
        float s = p.b[7][0];
        #pragma unroll 4
        for (int j = 0; j < HID; ++j)
            s = fmaf(act[tid * PADW + j], W7[j], s);
        out[row0 + tid] = 1.0f / (1.0f + expf(-s));
    }
}

// ---------------------------------------------------------------------------
extern "C" void kernel_launch(void* const* d_in, const int* in_sizes, int n_in,
                              void* d_out, int out_size) {
    const float* x  = (const float*)d_in[0];
    const void*  ei = d_in[1];
    Params p;
    for (int i = 0; i < 8; ++i) {
        p.W[i] = (const float*)d_in[2 + 2 * i];
        p.b[i] = (const float*)d_in[3 + 2 * i];
    }
    float* out = (float*)d_out;

    // opt-in to >48KB dynamic smem (idempotent, capture-safe)
    cudaFuncSetAttribute(mlp_kernel, cudaFuncAttributeMaxDynamicSharedMemorySize, SMEM_BYTES);

    detect_kernel<<<1, 32>>>((const int*)ei);
    zero_deg_kernel<<<NN / 256, 256>>>();
    deg_kernel<<<2048, 256>>>(ei);
    inv_init_kernel<<<NN / 256, 256>>>(x);
    edge_agg_kernel<<<2048, 256>>>(x, ei);
    mlp_kernel<<<NN / TM, 256, SMEM_BYTES>>>(p, out);
}

// round 2
// speedup vs baseline: 1.2780x; 1.2780x over previous
#include <cuda_runtime.h>
#include <math.h>

#define NN    262144
#define EE    2097152
#define HID   200
#define TM    64
#define PADW  208
#define KT    50           // k-tile size
#define KTP   50           // wt_t row stride (floats); 50 mod 32 = 18 -> conflict-free
#define NTILE 4            // 200 / 50
#define SMEM_BYTES ((TM * PADW + 2 * PADW * KTP) * 4)

typedef unsigned long long ull;

// Scratch (static device globals: allowed; no dynamic allocation anywhere)
__device__ float g_deg[NN];
__device__ float g_inv[NN];
__device__ float g_agg[NN];
__device__ int   g_is64;

struct Params {
    const float* W[8];
    const float* b[8];
};

// ---------------------------------------------------------------------------
// packed f32x2 FMA (FFMA2) — only reachable via PTX on sm_103a
// ---------------------------------------------------------------------------
__device__ __forceinline__ void fma2(ull& d, ull a, ull b) {
    asm("fma.rn.f32x2 %0, %1, %2, %0;" : "+l"(d) : "l"(a), "l"(b));
}

__device__ __forceinline__ void cp_async4(void* smem_dst, const void* gsrc) {
    unsigned sa = (unsigned)__cvta_generic_to_shared(smem_dst);
    asm volatile("cp.async.ca.shared.global [%0], [%1], 4;" :: "r"(sa), "l"(gsrc));
}
__device__ __forceinline__ void cp_commit() {
    asm volatile("cp.async.commit_group;");
}
__device__ __forceinline__ void cp_wait0() {
    asm volatile("cp.async.wait_group 0;");
}
__device__ __forceinline__ void cp_wait1() {
    asm volatile("cp.async.wait_group 1;");
}

// ---------------------------------------------------------------------------
// int64 vs int32 edge_index detection (values < 2^31 -> odd words all zero)
// ---------------------------------------------------------------------------
__global__ void detect_kernel(const int* __restrict__ ei32) {
    if (blockIdx.x == 0 && threadIdx.x == 0) {
        int orv = 0;
        for (int i = 1; i < 128; i += 2) orv |= ei32[i];
        g_is64 = (orv == 0) ? 1 : 0;
    }
}

__device__ __forceinline__ int load_idx(const void* ei, long long pos, int is64) {
    if (is64) return (int)((const long long*)ei)[pos];
    return ((const int*)ei)[pos];
}

__global__ void zero_deg_kernel() {
    int i = blockIdx.x * blockDim.x + threadIdx.x;
    if (i < NN) g_deg[i] = 0.0f;
}

__global__ void deg_kernel(const void* __restrict__ ei) {
    const int is64 = g_is64;
    long long stride = (long long)gridDim.x * blockDim.x;
    for (long long e = (long long)blockIdx.x * blockDim.x + threadIdx.x; e < EE; e += stride) {
        int d = load_idx(ei, (long long)EE + e, is64);
        atomicAdd(&g_deg[d], 1.0f);
    }
}

__global__ void inv_init_kernel(const float* __restrict__ x) {
    int i = blockIdx.x * blockDim.x + threadIdx.x;
    if (i < NN) {
        float inv = rsqrtf(g_deg[i] + 1.0f);
        g_inv[i] = inv;
        g_agg[i] = x[i] * inv * inv;          // self-loop message
    }
}

__global__ void edge_agg_kernel(const float* __restrict__ x, const void* __restrict__ ei) {
    const int is64 = g_is64;
    long long stride = (long long)gridDim.x * blockDim.x;
    for (long long e = (long long)blockIdx.x * blockDim.x + threadIdx.x; e < EE; e += stride) {
        int s = load_idx(ei, e, is64);
        int d = load_idx(ei, (long long)EE + e, is64);
        atomicAdd(&g_agg[d], x[s] * g_inv[s] * g_inv[d]);
    }
}

// ---------------------------------------------------------------------------
// Fused 8-layer MLP, K-packed FFMA2 micro-kernel.
// CTA = 64 rows x 256 threads (tr = tid>>4 -> 4 rows, tc = tid&15 -> 13 cols).
// Activations [64][208] row-major in smem (LDS.64 gives (a_k, a_k+1)).
// Weight tile transposed wt_t[j][kk] (LDS.64 gives (w_k_j, w_k+1_j)),
// double-buffered + staged with cp.async (transpose happens in flight).
// Each 64-bit accumulator holds (even-k, odd-k) partials, reduced at writeback.
// ---------------------------------------------------------------------------
__global__ void __launch_bounds__(256, 1) mlp_kernel(Params p, float* __restrict__ out) {
    extern __shared__ float sm[];
    float* act = sm;                       // TM x PADW
    float* wt0 = sm + TM * PADW;           // PADW x KTP (buffer 0)
    float* wt1 = wt0 + PADW * KTP;         // PADW x KTP (buffer 1)

    const int tid  = threadIdx.x;
    const int row0 = blockIdx.x * TM;
    const int tr4  = (tid >> 4) * 4;       // first of 4 rows
    const int tc   = tid & 15;

    // ---- layer 0: [N,1] @ [1,200] + b, relu ----
    {
        const float* W0 = p.W[0];
        const float* b0 = p.b[0];
        for (int idx = tid; idx < TM * PADW; idx += 256) {
            int r = idx / PADW;
            int j = idx - r * PADW;
            float v = 0.0f;
            if (j < HID) v = fmaxf(fmaf(g_agg[row0 + r], W0[j], b0[j]), 0.0f);
            act[idx] = v;
        }
        __syncthreads();
    }

    // ---- layers 1..6 ----
    for (int l = 1; l <= 6; ++l) {
        const float* __restrict__ W = p.W[l];
        const float* __restrict__ b = p.b[l];

        // stage tile 0 (transposed) into wt0
        for (int idx = tid; idx < KT * PADW; idx += 256) {
            int kk = idx / PADW;
            int j  = idx - kk * PADW;
            if (j < HID) cp_async4(&wt0[j * KTP + kk], &W[kk * HID + j]);
        }
        cp_commit();

        ull acc[4][13];
        #pragma unroll
        for (int i = 0; i < 4; ++i)
            #pragma unroll
            for (int m = 0; m < 13; ++m) acc[i][m] = 0ULL;

        for (int t = 0; t < NTILE; ++t) {
            float* cur = (t & 1) ? wt1 : wt0;
            float* nxt = (t & 1) ? wt0 : wt1;

            if (t < NTILE - 1) {
                int k0n = (t + 1) * KT;
                for (int idx = tid; idx < KT * PADW; idx += 256) {
                    int kk = idx / PADW;
                    int j  = idx - kk * PADW;
                    if (j < HID) cp_async4(&nxt[j * KTP + kk], &W[(k0n + kk) * HID + j]);
                }
                cp_commit();
                cp_wait1();            // tile t fully arrived
            } else {
                cp_wait0();
            }
            __syncthreads();           // make staged tile visible to all

            const int kbase = t * KT;
            #pragma unroll 5
            for (int kk = 0; kk < KT; kk += 2) {
                ull a2[4];
                #pragma unroll
                for (int i = 0; i < 4; ++i)
                    a2[i] = *reinterpret_cast<const ull*>(&act[(tr4 + i) * PADW + kbase + kk]);
                #pragma unroll
                for (int m = 0; m < 13; ++m) {
                    ull w2 = *reinterpret_cast<const ull*>(&cur[(tc + 16 * m) * KTP + kk]);
                    #pragma unroll
                    for (int i = 0; i < 4; ++i)
                        fma2(acc[i][m], a2[i], w2);
                }
            }
            __syncthreads();           // all reads of cur done before it's re-staged
        }

        // writeback: reduce (even,odd) halves, bias, relu
        #pragma unroll
        for (int i = 0; i < 4; ++i) {
            int r = tr4 + i;
            #pragma unroll
            for (int m = 0; m < 13; ++m) {
                int j = tc + 16 * m;
                if (j < HID) {
                    float lo = __int_as_float((int)(acc[i][m] & 0xffffffffULL));
                    float hi = __int_as_float((int)(acc[i][m] >> 32));
                    act[r * PADW + j] = fmaxf(lo + hi + b[j], 0.0f);
                }
            }
        }
        __syncthreads();
    }

    // ---- layer 7: [64,200] @ [200,1] + b, sigmoid ----
    if (tid < TM) {
        const float* __restrict__ W7 = p.W[7];
        float s = p.b[7][0];
        #pragma unroll 8
        for (int j = 0; j < HID; ++j)
            s = fmaf(act[tid * PADW + j], W7[j], s);
        out[row0 + tid] = 1.0f / (1.0f + expf(-s));
    }
}

// ---------------------------------------------------------------------------
extern "C" void kernel_launch(void* const* d_in, const int* in_sizes, int n_in,
                              void* d_out, int out_size) {
    const float* x  = (const float*)d_in[0];
    const void*  ei = d_in[1];
    Params p;
    for (int i = 0; i < 8; ++i) {
        p.W[i] = (const float*)d_in[2 + 2 * i];
        p.b[i] = (const float*)d_in[3 + 2 * i];
    }
    float* out = (float*)d_out;

    cudaFuncSetAttribute(mlp_kernel, cudaFuncAttributeMaxDynamicSharedMemorySize, SMEM_BYTES);

    detect_kernel<<<1, 32>>>((const int*)ei);
    zero_deg_kernel<<<NN / 256, 256>>>();
    deg_kernel<<<2048, 256>>>(ei);
    inv_init_kernel<<<NN / 256, 256>>>(x);
    edge_agg_kernel<<<2048, 256>>>(x, ei);
    mlp_kernel<<<NN / TM, 256, SMEM_BYTES>>>(p, out);
}

// round 4
// speedup vs baseline: 3.9663x; 3.1035x over previous
#include <cuda_runtime.h>
#include <cuda_bf16.h>
#include <math.h>
#include <stdint.h>

#define NN   262144
#define EE   2097152
#define HID  200
#define MT   128                 // rows per CTA
#define CAC  232                 // A smem cols (k padded; stride 464B conflict-free)
#define NCHK 7                   // k chunks of 32 (224 >= 200, zero padded)
#define BNC  216                 // B smem cols (n padded; stride 432B conflict-free)
#define SA_PLANE (MT * CAC * 2)          // 59392 B per A plane
#define SM_A_HI  0
#define SM_A_LO  SA_PLANE
#define SM_B     (2 * SA_PLANE)          // 118784
#define BPLANE   (32 * BNC * 2)          // 13824 B
#define BUFSZ    (2 * BPLANE)            // 27648 B (hi+lo)
#define SMEM_BYTES (SM_B + 2 * BUFSZ)    // 174080
#define THREADS  512

// ------------------------- device globals (scratch) -------------------------
__device__ float g_deg[NN];
__device__ float g_inv[NN];
__device__ float g_agg[NN];
__device__ int   g_is64;
// weights pre-split bf16 hi/lo: [layer 1..6][chunk][plane][k32][BNC]
__device__ __align__(16) __nv_bfloat16 g_wtB[6][NCHK][2][32][BNC];

struct Params {
    const float* W[8];
    const float* b[8];
};

// ------------------------------- PTX helpers --------------------------------
__device__ __forceinline__ uint32_t smem_u32(const void* p) {
    uint32_t a;
    asm("{ .reg .u64 t; cvta.to.shared.u64 t, %1; cvt.u32.u64 %0, t; }" : "=r"(a) : "l"(p));
    return a;
}
__device__ __forceinline__ void cp16(uint32_t sdst, const void* gsrc) {
    asm volatile("cp.async.cg.shared.global [%0], [%1], 16;" :: "r"(sdst), "l"(gsrc));
}
#define CP_COMMIT() asm volatile("cp.async.commit_group;")
#define CP_WAIT1()  asm volatile("cp.async.wait_group 1;")
#define CP_WAIT0()  asm volatile("cp.async.wait_group 0;")

__device__ __forceinline__ void ldsm_x4(uint32_t* r, uint32_t addr) {
    asm volatile("ldmatrix.sync.aligned.m8n8.x4.shared.b16 {%0,%1,%2,%3}, [%4];"
                 : "=r"(r[0]), "=r"(r[1]), "=r"(r[2]), "=r"(r[3]) : "r"(addr));
}
__device__ __forceinline__ void ldsm_x4t(uint32_t* r, uint32_t addr) {
    asm volatile("ldmatrix.sync.aligned.m8n8.x4.trans.shared.b16 {%0,%1,%2,%3}, [%4];"
                 : "=r"(r[0]), "=r"(r[1]), "=r"(r[2]), "=r"(r[3]) : "r"(addr));
}
__device__ __forceinline__ void ldsm_x2t(uint32_t* r, uint32_t addr) {
    asm volatile("ldmatrix.sync.aligned.m8n8.x2.trans.shared.b16 {%0,%1}, [%2];"
                 : "=r"(r[0]), "=r"(r[1]) : "r"(addr));
}
__device__ __forceinline__ void mma16816(float* d, const uint32_t* a, uint32_t b0, uint32_t b1) {
    asm volatile(
        "mma.sync.aligned.m16n8k16.row.col.f32.bf16.bf16.f32 "
        "{%0,%1,%2,%3}, {%4,%5,%6,%7}, {%8,%9}, {%0,%1,%2,%3};"
        : "+f"(d[0]), "+f"(d[1]), "+f"(d[2]), "+f"(d[3])
        : "r"(a[0]), "r"(a[1]), "r"(a[2]), "r"(a[3]), "r"(b0), "r"(b1));
}

// ------------------------- edge aggregation kernels -------------------------
__global__ void detect_kernel(const int* __restrict__ ei32) {
    if (blockIdx.x == 0 && threadIdx.x == 0) {
        int orv = 0;
        for (int i = 1; i < 128; i += 2) orv |= ei32[i];
        g_is64 = (orv == 0) ? 1 : 0;
    }
}
__device__ __forceinline__ int load_idx(const void* ei, long long pos, int is64) {
    if (is64) return (int)((const long long*)ei)[pos];
    return ((const int*)ei)[pos];
}
__global__ void zero_deg_kernel() {
    int i = blockIdx.x * blockDim.x + threadIdx.x;
    if (i < NN) g_deg[i] = 0.0f;
}
__global__ void deg_kernel(const void* __restrict__ ei) {
    const int is64 = g_is64;
    long long stride = (long long)gridDim.x * blockDim.x;
    for (long long e = (long long)blockIdx.x * blockDim.x + threadIdx.x; e < EE; e += stride) {
        int d = load_idx(ei, (long long)EE + e, is64);
        atomicAdd(&g_deg[d], 1.0f);
    }
}
__global__ void inv_init_kernel(const float* __restrict__ x) {
    int i = blockIdx.x * blockDim.x + threadIdx.x;
    if (i < NN) {
        float inv = rsqrtf(g_deg[i] + 1.0f);
        g_inv[i] = inv;
        g_agg[i] = x[i] * inv * inv;
    }
}
__global__ void edge_agg_kernel(const float* __restrict__ x, const void* __restrict__ ei) {
    const int is64 = g_is64;
    long long stride = (long long)gridDim.x * blockDim.x;
    for (long long e = (long long)blockIdx.x * blockDim.x + threadIdx.x; e < EE; e += stride) {
        int s = load_idx(ei, e, is64);
        int d = load_idx(ei, (long long)EE + e, is64);
        atomicAdd(&g_agg[d], x[s] * g_inv[s] * g_inv[d]);
    }
}

// ------------------- weight prep: fp32 -> bf16 hi/lo planes -----------------
__global__ void prep_w_kernel(Params p) {
    int idx = blockIdx.x * blockDim.x + threadIdx.x;
    const int total = 6 * NCHK * 32 * BNC;
    if (idx >= total) return;
    int n = idx % BNC;
    int k = (idx / BNC) % 32;
    int c = (idx / (BNC * 32)) % NCHK;
    int l = idx / (BNC * 32 * NCHK);
    int kg = c * 32 + k;
    float v = 0.0f;
    if (kg < HID && n < HID) v = p.W[l + 1][kg * HID + n];
    __nv_bfloat16 hi = __float2bfloat16(v);
    __nv_bfloat16 lo = __float2bfloat16(v - __bfloat162float(hi));
    g_wtB[l][c][0][k][n] = hi;
    g_wtB[l][c][1][k][n] = lo;
}

// ------------------------------ fused MLP kernel ----------------------------
__device__ __forceinline__ void split_store(char* sm, int r, int j, float v0, float v1) {
    __nv_bfloat16 h0 = __float2bfloat16(v0), h1 = __float2bfloat16(v1);
    __nv_bfloat16 l0 = __float2bfloat16(v0 - __bfloat162float(h0));
    __nv_bfloat16 l1 = __float2bfloat16(v1 - __bfloat162float(h1));
    uint32_t hp = (uint32_t)__bfloat16_as_ushort(h0) | ((uint32_t)__bfloat16_as_ushort(h1) << 16);
    uint32_t lp = (uint32_t)__bfloat16_as_ushort(l0) | ((uint32_t)__bfloat16_as_ushort(l1) << 16);
    *(uint32_t*)(sm + SM_A_HI + r * (CAC * 2) + j * 2) = hp;
    *(uint32_t*)(sm + SM_A_LO + r * (CAC * 2) + j * 2) = lp;
}

__global__ void __launch_bounds__(THREADS, 1) mlp_kernel(Params p, float* __restrict__ out) {
    extern __shared__ char sm[];
    const uint32_t sbase = smem_u32(sm);
    const int tid  = threadIdx.x;
    const int wid  = tid >> 5;
    const int lane = tid & 31;
    const int wr   = wid & 7;       // row group: rows 16*wr..+15
    const int wc   = wid >> 3;      // col half: cols 104*wc..+103
    const int row0 = blockIdx.x * MT;

    // ldmatrix lane address components
    const int mrow  = (lane & 7) + 8 * ((lane >> 3) & 1);
    const int koff8 = 8 * (lane >> 4);
    const uint32_t aHi = sbase + SM_A_HI + (wr * 16 + mrow) * (CAC * 2) + koff8 * 2;
    const uint32_t aLo = sbase + SM_A_LO + (wr * 16 + mrow) * (CAC * 2) + koff8 * 2;
    const uint32_t bOff = (uint32_t)(mrow * (BNC * 2) + koff8 * 2);  // +noff8 doubles as n offset

    // ---- layer 0: A = relu(agg * W0 + b0) -> bf16 hi/lo, zero padding ----
    {
        const float* W0 = p.W[0];
        const float* b0 = p.b[0];
        for (int idx = tid; idx < MT * (CAC / 2); idx += THREADS) {
            int r = idx / (CAC / 2);
            int j = (idx - r * (CAC / 2)) * 2;
            float agg = g_agg[row0 + r];
            float v0 = (j < HID)     ? fmaxf(fmaf(agg, W0[j],     b0[j]),     0.0f) : 0.0f;
            float v1 = (j + 1 < HID) ? fmaxf(fmaf(agg, W0[j + 1], b0[j + 1]), 0.0f) : 0.0f;
            split_store(sm, r, j, v0, v1);
        }
    }
    __syncthreads();

    for (int l = 1; l <= 6; ++l) {
        const __nv_bfloat16* wl = &g_wtB[l - 1][0][0][0][0];

        // stage chunk 0 into buffer 0
        for (int i = tid * 16; i < BUFSZ; i += THREADS * 16)
            cp16(sbase + SM_B + i, (const char*)wl + i);
        CP_COMMIT();

        float acc[13][4];
        #pragma unroll
        for (int t = 0; t < 13; ++t)
            #pragma unroll
            for (int q = 0; q < 4; ++q) acc[t][q] = 0.0f;

        for (int c = 0; c < NCHK; ++c) {
            const uint32_t curB = sbase + SM_B + (c & 1) * BUFSZ;
            if (c < NCHK - 1) {
                const char* src = (const char*)wl + (c + 1) * BUFSZ;
                uint32_t dst = sbase + SM_B + ((c + 1) & 1) * BUFSZ;
                for (int i = tid * 16; i < BUFSZ; i += THREADS * 16)
                    cp16(dst + i, src + i);
                CP_COMMIT();
                CP_WAIT1();
            } else {
                CP_WAIT0();
            }
            __syncthreads();   // chunk c visible to all warps

            #pragma unroll
            for (int ks = 0; ks < 2; ++ks) {
                const int kb = c * 32 + ks * 16;
                uint32_t ah[4], al[4];
                ldsm_x4(ah, aHi + kb * 2);
                ldsm_x4(al, aLo + kb * 2);
                const uint32_t bk = curB + bOff + ks * 16 * (BNC * 2);
                #pragma unroll
                for (int pr = 0; pr < 6; ++pr) {
                    const int nc = wc * 104 + pr * 16;
                    uint32_t bh[4], bl[4];
                    ldsm_x4t(bh, bk + nc * 2);
                    ldsm_x4t(bl, bk + BPLANE + nc * 2);
                    mma16816(acc[2 * pr],     ah, bh[0], bh[1]);
                    mma16816(acc[2 * pr],     ah, bl[0], bl[1]);
                    mma16816(acc[2 * pr],     al, bh[0], bh[1]);
                    mma16816(acc[2 * pr + 1], ah, bh[2], bh[3]);
                    mma16816(acc[2 * pr + 1], ah, bl[2], bl[3]);
                    mma16816(acc[2 * pr + 1], al, bh[2], bh[3]);
                }
                if (wc == 0) {          // 13th n-tile (cols 96-103) only in half 0
                    uint32_t bh2[2], bl2[2];
                    ldsm_x2t(bh2, bk + 96 * 2);
                    ldsm_x2t(bl2, bk + BPLANE + 96 * 2);
                    mma16816(acc[12], ah, bh2[0], bh2[1]);
                    mma16816(acc[12], ah, bl2[0], bl2[1]);
                    mma16816(acc[12], al, bh2[0], bh2[1]);
                }
            }
            __syncthreads();   // all reads of curB done before it is restaged
        }

        const int r0 = wr * 16 + (lane >> 2);
        const int r1 = r0 + 8;

        if (l < 6) {
            // epilogue: bias + relu + hi/lo split back into A
            const float* bias = p.b[l];
            #pragma unroll
            for (int t = 0; t < 13; ++t) {
                int j = wc * 104 + t * 8 + 2 * (lane & 3);
                if (j < HID) {
                    float bj0 = bias[j], bj1 = (j + 1 < HID) ? bias[j + 1] : 0.0f;
                    float v0 = fmaxf(acc[t][0] + bj0, 0.0f);
                    float v1 = (j + 1 < HID) ? fmaxf(acc[t][1] + bj1, 0.0f) : 0.0f;
                    split_store(sm, r0, j, v0, v1);
                    float v2 = fmaxf(acc[t][2] + bj0, 0.0f);
                    float v3 = (j + 1 < HID) ? fmaxf(acc[t][3] + bj1, 0.0f) : 0.0f;
                    split_store(sm, r1, j, v2, v3);
                }
            }
            __syncthreads();   // A ready for next layer's ldmatrix
        } else {
            // final: relu(acc + b6) dot W7 -> reduce -> sigmoid
            const float* bias = p.b[6];
            const float* W7   = p.W[7];
            float p0 = 0.0f, p1 = 0.0f;
            #pragma unroll
            for (int t = 0; t < 13; ++t) {
                int j = wc * 104 + t * 8 + 2 * (lane & 3);
                if (j < HID) {
                    float bj0 = bias[j], w0 = W7[j];
                    p0 = fmaf(fmaxf(acc[t][0] + bj0, 0.0f), w0, p0);
                    p1 = fmaf(fmaxf(acc[t][2] + bj0, 0.0f), w0, p1);
                    if (j + 1 < HID) {
                        float bj1 = bias[j + 1], w1 = W7[j + 1];
                        p0 = fmaf(fmaxf(acc[t][1] + bj1, 0.0f), w1, p0);
                        p1 = fmaf(fmaxf(acc[t][3] + bj1, 0.0f), w1, p1);
                    }
                }
            }
            p0 += __shfl_xor_sync(0xffffffff, p0, 1);
            p0 += __shfl_xor_sync(0xffffffff, p0, 2);
            p1 += __shfl_xor_sync(0xffffffff, p1, 1);
            p1 += __shfl_xor_sync(0xffffffff, p1, 2);
            float* red = (float*)(sm + SM_B);
            if ((lane & 3) == 0) {
                red[r0 * 2 + wc] = p0;
                red[r1 * 2 + wc] = p1;
            }
            __syncthreads();
            if (tid < MT) {
                float s = red[tid * 2] + red[tid * 2 + 1] + p.b[7][0];
                out[row0 + tid] = 1.0f / (1.0f + expf(-s));
            }
        }
    }
}

// ---------------------------------------------------------------------------
extern "C" void kernel_launch(void* const* d_in, const int* in_sizes, int n_in,
                              void* d_out, int out_size) {
    const float* x  = (const float*)d_in[0];
    const void*  ei = d_in[1];
    Params p;
    for (int i = 0; i < 8; ++i) {
        p.W[i] = (const float*)d_in[2 + 2 * i];
        p.b[i] = (const float*)d_in[3 + 2 * i];
    }
    float* out = (float*)d_out;

    cudaFuncSetAttribute(mlp_kernel, cudaFuncAttributeMaxDynamicSharedMemorySize, SMEM_BYTES);

    detect_kernel<<<1, 32>>>((const int*)ei);
    prep_w_kernel<<<(6 * NCHK * 32 * BNC + 255) / 256, 256>>>(p);
    zero_deg_kernel<<<NN / 256, 256>>>();
    deg_kernel<<<2048, 256>>>(ei);
    inv_init_kernel<<<NN / 256, 256>>>(x);
    edge_agg_kernel<<<2048, 256>>>(x, ei);
    mlp_kernel<<<NN / MT, THREADS, SMEM_BYTES>>>(p, out);
}

// round 8
// speedup vs baseline: 4.1434x; 1.0447x over previous
#include <cuda_runtime.h>
#include <cuda_bf16.h>
#include <math.h>
#include <stdint.h>

#define NN   262144
#define EE   2097152
#define HID  200
#define MT   128                 // rows per CTA
#define CAC  232                 // A smem cols (k padded; stride 464B conflict-free)
#define NCHK 7                   // k chunks of 32 (224 >= 200, zero padded)
#define BNC  216                 // B smem cols (n padded; stride 432B conflict-free)
#define SA_PLANE (MT * CAC * 2)          // 59392 B per A plane
#define SM_A_HI  0
#define SM_A_LO  SA_PLANE
#define SM_B     (2 * SA_PLANE)          // 118784
#define BPLANE   (32 * BNC * 2)          // 13824 B
#define BUFSZ    (2 * BPLANE)            // 27648 B (hi+lo)
#define SMEM_BYTES (SM_B + 2 * BUFSZ)    // 174080
#define THREADS  256

// ------------------------- device globals (scratch) -------------------------
__device__ float g_deg[NN];
__device__ float g_inv[NN];
__device__ float g_agg[NN];
__device__ int   g_is64;
// weights pre-split bf16 hi/lo: [layer 1..6][chunk][plane][k32][BNC]
__device__ __align__(16) __nv_bfloat16 g_wtB[6][NCHK][2][32][BNC];

struct Params {
    const float* W[8];
    const float* b[8];
};

// ------------------------------- PTX helpers --------------------------------
__device__ __forceinline__ uint32_t smem_u32(const void* p) {
    uint32_t a;
    asm("{ .reg .u64 t; cvta.to.shared.u64 t, %1; cvt.u32.u64 %0, t; }" : "=r"(a) : "l"(p));
    return a;
}
__device__ __forceinline__ void cp16(uint32_t sdst, const void* gsrc) {
    asm volatile("cp.async.cg.shared.global [%0], [%1], 16;" :: "r"(sdst), "l"(gsrc));
}
#define CP_COMMIT() asm volatile("cp.async.commit_group;")
#define CP_WAIT1()  asm volatile("cp.async.wait_group 1;")
#define CP_WAIT0()  asm volatile("cp.async.wait_group 0;")

__device__ __forceinline__ void ldsm_x4(uint32_t* r, uint32_t addr) {
    asm volatile("ldmatrix.sync.aligned.m8n8.x4.shared.b16 {%0,%1,%2,%3}, [%4];"
                 : "=r"(r[0]), "=r"(r[1]), "=r"(r[2]), "=r"(r[3]) : "r"(addr));
}
__device__ __forceinline__ void ldsm_x4t(uint32_t* r, uint32_t addr) {
    asm volatile("ldmatrix.sync.aligned.m8n8.x4.trans.shared.b16 {%0,%1,%2,%3}, [%4];"
                 : "=r"(r[0]), "=r"(r[1]), "=r"(r[2]), "=r"(r[3]) : "r"(addr));
}
__device__ __forceinline__ void ldsm_x2t(uint32_t* r, uint32_t addr) {
    asm volatile("ldmatrix.sync.aligned.m8n8.x2.trans.shared.b16 {%0,%1}, [%2];"
                 : "=r"(r[0]), "=r"(r[1]) : "r"(addr));
}
__device__ __forceinline__ void mma16816(float* d, const uint32_t* a, uint32_t b0, uint32_t b1) {
    asm volatile(
        "mma.sync.aligned.m16n8k16.row.col.f32.bf16.bf16.f32 "
        "{%0,%1,%2,%3}, {%4,%5,%6,%7}, {%8,%9}, {%0,%1,%2,%3};"
        : "+f"(d[0]), "+f"(d[1]), "+f"(d[2]), "+f"(d[3])
        : "r"(a[0]), "r"(a[1]), "r"(a[2]), "r"(a[3]), "r"(b0), "r"(b1));
}

// ------------------------- edge aggregation kernels -------------------------
__global__ void detect_kernel(const int* __restrict__ ei32) {
    if (blockIdx.x == 0 && threadIdx.x == 0) {
        int orv = 0;
        for (int i = 1; i < 128; i += 2) orv |= ei32[i];
        g_is64 = (orv == 0) ? 1 : 0;
    }
}
__device__ __forceinline__ int load_idx(const void* ei, long long pos, int is64) {
    if (is64) return (int)((const long long*)ei)[pos];
    return ((const int*)ei)[pos];
}
__global__ void zero_deg_kernel() {
    int i = blockIdx.x * blockDim.x + threadIdx.x;
    if (i < NN) g_deg[i] = 0.0f;
}
__global__ void deg_kernel(const void* __restrict__ ei) {
    const int is64 = g_is64;
    long long stride = (long long)gridDim.x * blockDim.x;
    for (long long e = (long long)blockIdx.x * blockDim.x + threadIdx.x; e < EE; e += stride) {
        int d = load_idx(ei, (long long)EE + e, is64);
        atomicAdd(&g_deg[d], 1.0f);
    }
}
__global__ void inv_init_kernel(const float* __restrict__ x) {
    int i = blockIdx.x * blockDim.x + threadIdx.x;
    if (i < NN) {
        float inv = rsqrtf(g_deg[i] + 1.0f);
        g_inv[i] = inv;
        g_agg[i] = x[i] * inv * inv;
    }
}
__global__ void edge_agg_kernel(const float* __restrict__ x, const void* __restrict__ ei) {
    const int is64 = g_is64;
    long long stride = (long long)gridDim.x * blockDim.x;
    for (long long e = (long long)blockIdx.x * blockDim.x + threadIdx.x; e < EE; e += stride) {
        int s = load_idx(ei, e, is64);
        int d = load_idx(ei, (long long)EE + e, is64);
        atomicAdd(&g_agg[d], x[s] * g_inv[s] * g_inv[d]);
    }
}

// ------------------- weight prep: fp32 -> bf16 hi/lo planes -----------------
__global__ void prep_w_kernel(Params p) {
    int idx = blockIdx.x * blockDim.x + threadIdx.x;
    const int total = 6 * NCHK * 32 * BNC;
    if (idx >= total) return;
    int n = idx % BNC;
    int k = (idx / BNC) % 32;
    int c = (idx / (BNC * 32)) % NCHK;
    int l = idx / (BNC * 32 * NCHK);
    int kg = c * 32 + k;
    float v = 0.0f;
    if (kg < HID && n < HID) v = p.W[l + 1][kg * HID + n];
    __nv_bfloat16 hi = __float2bfloat16(v);
    __nv_bfloat16 lo = __float2bfloat16(v - __bfloat162float(hi));
    g_wtB[l][c][0][k][n] = hi;
    g_wtB[l][c][1][k][n] = lo;
}

// ------------------------------ fused MLP kernel ----------------------------
__device__ __forceinline__ void split_store(char* sm, int r, int j, float v0, float v1) {
    __nv_bfloat16 h0 = __float2bfloat16(v0), h1 = __float2bfloat16(v1);
    __nv_bfloat16 l0 = __float2bfloat16(v0 - __bfloat162float(h0));
    __nv_bfloat16 l1 = __float2bfloat16(v1 - __bfloat162float(h1));
    uint32_t hp = (uint32_t)__bfloat16_as_ushort(h0) | ((uint32_t)__bfloat16_as_ushort(h1) << 16);
    uint32_t lp = (uint32_t)__bfloat16_as_ushort(l0) | ((uint32_t)__bfloat16_as_ushort(l1) << 16);
    *(uint32_t*)(sm + SM_A_HI + r * (CAC * 2) + j * 2) = hp;
    *(uint32_t*)(sm + SM_A_LO + r * (CAC * 2) + j * 2) = lp;
}

__global__ void __launch_bounds__(THREADS, 1) mlp_kernel(Params p, float* __restrict__ out) {
    extern __shared__ char sm[];
    const uint32_t sbase = smem_u32(sm);
    const int tid  = threadIdx.x;
    const int wid  = tid >> 5;
    const int lane = tid & 31;
    const int wr   = wid & 3;       // row group: rows 32*wr..+31 (two m16 subtiles)
    const int wc   = wid >> 2;      // col half: cols 104*wc..+103
    const int row0 = blockIdx.x * MT;

    // ldmatrix lane address components
    const int mrow  = (lane & 7) + 8 * ((lane >> 3) & 1);
    const int koff8 = 8 * (lane >> 4);
    const uint32_t aHi0 = sbase + SM_A_HI + (wr * 32 + mrow) * (CAC * 2) + koff8 * 2;
    const uint32_t aLo0 = sbase + SM_A_LO + (wr * 32 + mrow) * (CAC * 2) + koff8 * 2;
    const uint32_t aHi1 = aHi0 + 16 * (CAC * 2);
    const uint32_t aLo1 = aLo0 + 16 * (CAC * 2);
    const uint32_t bOff = (uint32_t)(mrow * (BNC * 2) + koff8 * 2);

    // ---- layer 0: A = relu(agg * W0 + b0) -> bf16 hi/lo, zero padding ----
    {
        const float* W0 = p.W[0];
        const float* b0 = p.b[0];
        for (int idx = tid; idx < MT * (CAC / 2); idx += THREADS) {
            int r = idx / (CAC / 2);
            int j = (idx - r * (CAC / 2)) * 2;
            float agg = g_agg[row0 + r];
            float v0 = (j < HID)     ? fmaxf(fmaf(agg, W0[j],     b0[j]),     0.0f) : 0.0f;
            float v1 = (j + 1 < HID) ? fmaxf(fmaf(agg, W0[j + 1], b0[j + 1]), 0.0f) : 0.0f;
            split_store(sm, r, j, v0, v1);
        }
    }
    __syncthreads();

    for (int l = 1; l <= 6; ++l) {
        const __nv_bfloat16* wl = &g_wtB[l - 1][0][0][0][0];

        // stage chunk 0 into buffer 0
        for (int i = tid * 16; i < BUFSZ; i += THREADS * 16)
            cp16(sbase + SM_B + i, (const char*)wl + i);
        CP_COMMIT();

        float acc[2][13][4];
        #pragma unroll
        for (int s = 0; s < 2; ++s)
            #pragma unroll
            for (int t = 0; t < 13; ++t)
                #pragma unroll
                for (int q = 0; q < 4; ++q) acc[s][t][q] = 0.0f;

        for (int c = 0; c < NCHK; ++c) {
            const uint32_t curB = sbase + SM_B + (c & 1) * BUFSZ;
            if (c < NCHK - 1) {
                const char* src = (const char*)wl + (c + 1) * BUFSZ;
                uint32_t dst = sbase + SM_B + ((c + 1) & 1) * BUFSZ;
                for (int i = tid * 16; i < BUFSZ; i += THREADS * 16)
                    cp16(dst + i, src + i);
                CP_COMMIT();
                CP_WAIT1();
            } else {
                CP_WAIT0();
            }
            __syncthreads();   // chunk c visible to all warps

            #pragma unroll
            for (int ks = 0; ks < 2; ++ks) {
                const int kb = c * 32 + ks * 16;
                uint32_t ah[2][4], al[2][4];
                ldsm_x4(ah[0], aHi0 + kb * 2);
                ldsm_x4(ah[1], aHi1 + kb * 2);
                ldsm_x4(al[0], aLo0 + kb * 2);
                ldsm_x4(al[1], aLo1 + kb * 2);
                const uint32_t bk = curB + bOff + ks * 16 * (BNC * 2);
                #pragma unroll
                for (int pr = 0; pr < 6; ++pr) {
                    const int nc = wc * 104 + pr * 16;
                    uint32_t bh[4], bl[4];
                    ldsm_x4t(bh, bk + nc * 2);
                    ldsm_x4t(bl, bk + BPLANE + nc * 2);
                    #pragma unroll
                    for (int s = 0; s < 2; ++s) {
                        mma16816(acc[s][2 * pr],     ah[s], bh[0], bh[1]);
                        mma16816(acc[s][2 * pr],     ah[s], bl[0], bl[1]);
                        mma16816(acc[s][2 * pr],     al[s], bh[0], bh[1]);
                        mma16816(acc[s][2 * pr + 1], ah[s], bh[2], bh[3]);
                        mma16816(acc[s][2 * pr + 1], ah[s], bl[2], bl[3]);
                        mma16816(acc[s][2 * pr + 1], al[s], bh[2], bh[3]);
                    }
                }
                if (wc == 0) {          // 13th n-tile (cols 96-103) only in half 0
                    uint32_t bh2[2], bl2[2];
                    ldsm_x2t(bh2, bk + 96 * 2);
                    ldsm_x2t(bl2, bk + BPLANE + 96 * 2);
                    #pragma unroll
                    for (int s = 0; s < 2; ++s) {
                        mma16816(acc[s][12], ah[s], bh2[0], bh2[1]);
                        mma16816(acc[s][12], ah[s], bl2[0], bl2[1]);
                        mma16816(acc[s][12], al[s], bh2[0], bh2[1]);
                    }
                }
            }
            __syncthreads();   // all reads of curB done before it is restaged
        }

        if (l < 6) {
            // epilogue: bias + relu + hi/lo split back into A
            const float* bias = p.b[l];
            #pragma unroll
            for (int s = 0; s < 2; ++s) {
                const int r0 = wr * 32 + s * 16 + (lane >> 2);
                const int r1 = r0 + 8;
                #pragma unroll
                for (int t = 0; t < 13; ++t) {
                    int j = wc * 104 + t * 8 + 2 * (lane & 3);
                    if (j < HID) {
                        float bj0 = bias[j], bj1 = (j + 1 < HID) ? bias[j + 1] : 0.0f;
                        float v0 = fmaxf(acc[s][t][0] + bj0, 0.0f);
                        float v1 = (j + 1 < HID) ? fmaxf(acc[s][t][1] + bj1, 0.0f) : 0.0f;
                        split_store(sm, r0, j, v0, v1);
                        float v2 = fmaxf(acc[s][t][2] + bj0, 0.0f);
                        float v3 = (j + 1 < HID) ? fmaxf(acc[s][t][3] + bj1, 0.0f) : 0.0f;
                        split_store(sm, r1, j, v2, v3);
                    }
                }
            }
            __syncthreads();   // A ready for next layer's ldmatrix
        } else {
            // final: relu(acc + b6) dot W7 -> reduce -> sigmoid
            const float* bias = p.b[6];
            const float* W7   = p.W[7];
            float* red = (float*)(sm + SM_B);
            #pragma unroll
            for (int s = 0; s < 2; ++s) {
                const int r0 = wr * 32 + s * 16 + (lane >> 2);
                const int r1 = r0 + 8;
                float p0 = 0.0f, p1 = 0.0f;
                #pragma unroll
                for (int t = 0; t < 13; ++t) {
                    int j = wc * 104 + t * 8 + 2 * (lane & 3);
                    if (j < HID) {
                        float bj0 = bias[j], w0 = W7[j];
                        p0 = fmaf(fmaxf(acc[s][t][0] + bj0, 0.0f), w0, p0);
                        p1 = fmaf(fmaxf(acc[s][t][2] + bj0, 0.0f), w0, p1);
                        if (j + 1 < HID) {
                            float bj1 = bias[j + 1], w1 = W7[j + 1];
                            p0 = fmaf(fmaxf(acc[s][t][1] + bj1, 0.0f), w1, p0);
                            p1 = fmaf(fmaxf(acc[s][t][3] + bj1, 0.0f), w1, p1);
                        }
                    }
                }
                p0 += __shfl_xor_sync(0xffffffff, p0, 1);
                p0 += __shfl_xor_sync(0xffffffff, p0, 2);
                p1 += __shfl_xor_sync(0xffffffff, p1, 1);
                p1 += __shfl_xor_sync(0xffffffff, p1, 2);
                if ((lane & 3) == 0) {
                    red[r0 * 2 + wc] = p0;
                    red[r1 * 2 + wc] = p1;
                }
            }
            __syncthreads();
            if (tid < MT) {
                float s = red[tid * 2] + red[tid * 2 + 1] + p.b[7][0];
                out[row0 + tid] = 1.0f / (1.0f + expf(-s));
            }
        }
    }
}

// ---------------------------------------------------------------------------
extern "C" void kernel_launch(void* const* d_in, const int* in_sizes, int n_in,
                              void* d_out, int out_size) {
    const float* x  = (const float*)d_in[0];
    const void*  ei = d_in[1];
    Params p;
    for (int i = 0; i < 8; ++i) {
        p.W[i] = (const float*)d_in[2 + 2 * i];
        p.b[i] = (const float*)d_in[3 + 2 * i];
    }
    float* out = (float*)d_out;

    cudaFuncSetAttribute(mlp_kernel, cudaFuncAttributeMaxDynamicSharedMemorySize, SMEM_BYTES);

    detect_kernel<<<1, 32>>>((const int*)ei);
    prep_w_kernel<<<(6 * NCHK * 32 * BNC + 255) / 256, 256>>>(p);
    zero_deg_kernel<<<NN / 256, 256>>>();
    deg_kernel<<<2048, 256>>>(ei);
    inv_init_kernel<<<NN / 256, 256>>>(x);
    edge_agg_kernel<<<2048, 256>>>(x, ei);
    mlp_kernel<<<NN / MT, THREADS, SMEM_BYTES>>>(p, out);
}